// round 1
// baseline (speedup 1.0000x reference)
#include <cuda_runtime.h>
#include <math.h>

#define ED 1024
#define NB 2
#define SEQ 4096
#define MTOT (NB * SEQ)

// Scratch (static device globals — allocation guards forbid cudaMalloc)
__device__ float g_Q[(size_t)MTOT * ED];
__device__ float g_K[(size_t)MTOT * ED];
__device__ float g_V[(size_t)MTOT * ED];
__device__ float g_O[(size_t)MTOT * ED];
__device__ float g_S[(size_t)NB * SEQ * SEQ];   // 128 MB attention scores

// ---------------------------------------------------------------------------
// Tiled SGEMM.
//  BT = true : C[M,N] = alpha * A[M,K] * B[N,K]^T   (both row-major, K-contig)
//  BT = false: C[M,N] = alpha * A[M,K] * B[K,N]     (row-major)
// Block tile 128x128x16, 256 threads, 8x8 per-thread register tile.
// Requires M%128==0, N%128==0, K%16==0 (true for all shapes here).
// Batch via blockIdx.z with element strides sA/sB/sC.
// ---------------------------------------------------------------------------
template <bool BT>
__global__ __launch_bounds__(256, 2) void gemm_tile(
    const float* __restrict__ A, const float* __restrict__ Bp,
    float* __restrict__ C, int M, int N, int K, float alpha,
    size_t sA, size_t sB, size_t sC)
{
    constexpr int BK = 16;
    __shared__ __align__(16) float As[BK][128];
    __shared__ __align__(16) float Bs[BK][128];

    A  += (size_t)blockIdx.z * sA;
    Bp += (size_t)blockIdx.z * sB;
    C  += (size_t)blockIdx.z * sC;

    const int tid = threadIdx.x;
    const int blockRow = blockIdx.y;
    const int blockCol = blockIdx.x;
    const int tr = tid >> 4;      // 0..15
    const int tc = tid & 15;      // 0..15

    float acc[8][8];
#pragma unroll
    for (int i = 0; i < 8; i++)
#pragma unroll
        for (int j = 0; j < 8; j++) acc[i][j] = 0.0f;

    const float* Atile = A + (size_t)blockRow * 128 * K;
    const float* BtileT = BT ? (Bp + (size_t)blockCol * 128 * K) : Bp;

    for (int k0 = 0; k0 < K; k0 += BK) {
        // ---- load A tile (128 x 16), store transposed As[k][m] ----
#pragma unroll
        for (int it = 0; it < 2; it++) {
            int idx = tid + it * 256;
            int row = idx >> 2;         // 4 float4 per row of 16
            int c4  = idx & 3;
            float4 v = *(const float4*)(Atile + (size_t)row * K + k0 + c4 * 4);
            As[c4 * 4 + 0][row] = v.x;
            As[c4 * 4 + 1][row] = v.y;
            As[c4 * 4 + 2][row] = v.z;
            As[c4 * 4 + 3][row] = v.w;
        }
        // ---- load B tile ----
        if (BT) {
            // B is [N,K] row-major: tile 128 rows (n) x 16 cols (k), transpose
#pragma unroll
            for (int it = 0; it < 2; it++) {
                int idx = tid + it * 256;
                int row = idx >> 2;
                int c4  = idx & 3;
                float4 v = *(const float4*)(BtileT + (size_t)row * K + k0 + c4 * 4);
                Bs[c4 * 4 + 0][row] = v.x;
                Bs[c4 * 4 + 1][row] = v.y;
                Bs[c4 * 4 + 2][row] = v.z;
                Bs[c4 * 4 + 3][row] = v.w;
            }
        } else {
            // B is [K,N] row-major: tile 16 rows (k) x 128 cols (n), direct
#pragma unroll
            for (int it = 0; it < 2; it++) {
                int idx = tid + it * 256;
                int row = idx >> 5;     // 32 float4 per 128-col row
                int c4  = idx & 31;
                float4 v = *(const float4*)(Bp + (size_t)(k0 + row) * N
                                            + (size_t)blockCol * 128 + c4 * 4);
                *(float4*)&Bs[row][c4 * 4] = v;
            }
        }
        __syncthreads();

#pragma unroll
        for (int kk = 0; kk < BK; kk++) {
            float ra[8], rb[8];
            *(float4*)&ra[0] = *(const float4*)&As[kk][tr * 8];
            *(float4*)&ra[4] = *(const float4*)&As[kk][tr * 8 + 4];
            *(float4*)&rb[0] = *(const float4*)&Bs[kk][tc * 8];
            *(float4*)&rb[4] = *(const float4*)&Bs[kk][tc * 8 + 4];
#pragma unroll
            for (int i = 0; i < 8; i++)
#pragma unroll
                for (int j = 0; j < 8; j++)
                    acc[i][j] = fmaf(ra[i], rb[j], acc[i][j]);
        }
        __syncthreads();
    }

    // ---- epilogue ----
#pragma unroll
    for (int i = 0; i < 8; i++) {
        size_t row = (size_t)blockRow * 128 + tr * 8 + i;
        float4 o0, o1;
        o0.x = acc[i][0] * alpha; o0.y = acc[i][1] * alpha;
        o0.z = acc[i][2] * alpha; o0.w = acc[i][3] * alpha;
        o1.x = acc[i][4] * alpha; o1.y = acc[i][5] * alpha;
        o1.z = acc[i][6] * alpha; o1.w = acc[i][7] * alpha;
        float* cp = C + row * N + (size_t)blockCol * 128 + tc * 8;
        *(float4*)cp       = o0;
        *(float4*)(cp + 4) = o1;
    }
}

// ---------------------------------------------------------------------------
// Row softmax over 4096 elements. One 256-thread block per row.
// Row kept in registers (16 floats/thread).
// ---------------------------------------------------------------------------
__global__ __launch_bounds__(256) void softmax_row(float* __restrict__ Sm)
{
    float* p = Sm + (size_t)blockIdx.x * SEQ;
    const int tid = threadIdx.x;
    __shared__ float red[8];

    float4 v[4];
    float m = -1e30f;
#pragma unroll
    for (int i = 0; i < 4; i++) {
        v[i] = *(const float4*)(p + (size_t)(i * 256 + tid) * 4);
        m = fmaxf(m, fmaxf(fmaxf(v[i].x, v[i].y), fmaxf(v[i].z, v[i].w)));
    }
    // block max
#pragma unroll
    for (int o = 16; o; o >>= 1) m = fmaxf(m, __shfl_xor_sync(0xFFFFFFFFu, m, o));
    if ((tid & 31) == 0) red[tid >> 5] = m;
    __syncthreads();
    m = red[0];
#pragma unroll
    for (int w = 1; w < 8; w++) m = fmaxf(m, red[w]);
    __syncthreads();

    float s = 0.0f;
#pragma unroll
    for (int i = 0; i < 4; i++) {
        v[i].x = __expf(v[i].x - m); v[i].y = __expf(v[i].y - m);
        v[i].z = __expf(v[i].z - m); v[i].w = __expf(v[i].w - m);
        s += v[i].x + v[i].y + v[i].z + v[i].w;
    }
#pragma unroll
    for (int o = 16; o; o >>= 1) s += __shfl_xor_sync(0xFFFFFFFFu, s, o);
    if ((tid & 31) == 0) red[tid >> 5] = s;
    __syncthreads();
    s = red[0];
#pragma unroll
    for (int w = 1; w < 8; w++) s += red[w];

    const float r = 1.0f / s;
#pragma unroll
    for (int i = 0; i < 4; i++) {
        v[i].x *= r; v[i].y *= r; v[i].z *= r; v[i].w *= r;
        *(float4*)(p + (size_t)(i * 256 + tid) * 4) = v[i];
    }
}

// ---------------------------------------------------------------------------
extern "C" void kernel_launch(void* const* d_in, const int* in_sizes, int n_in,
                              void* d_out, int out_size)
{
    const float* x  = (const float*)d_in[0];
    const float* Wq = (const float*)d_in[1];
    const float* Wk = (const float*)d_in[2];
    const float* Wv = (const float*)d_in[3];
    const float* Wo = (const float*)d_in[4];
    float* out = (float*)d_out;

    float *Q, *K, *V, *O, *Smat;
    cudaGetSymbolAddress((void**)&Q,    g_Q);
    cudaGetSymbolAddress((void**)&K,    g_K);
    cudaGetSymbolAddress((void**)&V,    g_V);
    cudaGetSymbolAddress((void**)&O,    g_O);
    cudaGetSymbolAddress((void**)&Smat, g_S);

    const size_t sQKV = (size_t)SEQ * ED;        // per-batch stride for Q/K/V/O
    const size_t sS   = (size_t)SEQ * SEQ;       // per-batch stride for scores

    // 1) QKV projections: [8192,1024] = x[8192,1024] @ W[1024,1024]^T
    {
        dim3 grid(ED / 128, MTOT / 128, 1);
        gemm_tile<true><<<grid, 256>>>(x, Wq, Q, MTOT, ED, ED, 1.0f, 0, 0, 0);
        gemm_tile<true><<<grid, 256>>>(x, Wk, K, MTOT, ED, ED, 1.0f, 0, 0, 0);
        gemm_tile<true><<<grid, 256>>>(x, Wv, V, MTOT, ED, ED, 1.0f, 0, 0, 0);
    }

    // 2) Scores: S[b] = Q[b] @ K[b]^T / 32     (4096x4096, K=1024), batched
    {
        dim3 grid(SEQ / 128, SEQ / 128, NB);
        gemm_tile<true><<<grid, 256>>>(Q, K, Smat, SEQ, SEQ, ED, 0.03125f,
                                       sQKV, sQKV, sS);
    }

    // 3) Softmax along last axis
    softmax_row<<<NB * SEQ, 256>>>(Smat);

    // 4) O[b] = S[b] @ V[b]                    (4096x1024, K=4096), batched
    {
        dim3 grid(ED / 128, SEQ / 128, NB);
        gemm_tile<false><<<grid, 256>>>(Smat, V, O, SEQ, ED, SEQ, 1.0f,
                                        sS, sQKV, sQKV);
    }

    // 5) Output projection: out = O @ Wo^T     ([8192,1024])
    {
        dim3 grid(ED / 128, MTOT / 128, 1);
        gemm_tile<true><<<grid, 256>>>(O, Wo, out, MTOT, ED, ED, 1.0f, 0, 0, 0);
    }
}

// round 3
// speedup vs baseline: 3.0391x; 3.0391x over previous
#include <cuda_runtime.h>
#include <cuda_fp16.h>
#include <math.h>
#include <stdint.h>

#define ED 1024
#define NB 2
#define SEQ 4096
#define MTOT (NB * SEQ)

// ---------------- scratch (static device globals; no allocs allowed) -------
__device__ __half g_xhi[(size_t)MTOT * ED];
__device__ __half g_xlo[(size_t)MTOT * ED];
__device__ __half g_Whi[4][(size_t)ED * ED];   // q,k,v,o
__device__ __half g_Wlo[4][(size_t)ED * ED];
__device__ __half g_Qhi[(size_t)MTOT * ED];
__device__ __half g_Qlo[(size_t)MTOT * ED];
__device__ __half g_Khi[(size_t)MTOT * ED];
__device__ __half g_Klo[(size_t)MTOT * ED];
__device__ __half g_Vthi[(size_t)MTOT * ED];   // [b][d][s] transposed
__device__ __half g_Vtlo[(size_t)MTOT * ED];
__device__ __half g_Ohi[(size_t)MTOT * ED];
__device__ __half g_Olo[(size_t)MTOT * ED];
__device__ float  g_S  [(size_t)NB * SEQ * SEQ];   // fp32 scores
__device__ __half g_Phi[(size_t)NB * SEQ * SEQ];
__device__ __half g_Plo[(size_t)NB * SEQ * SEQ];

// ---------------- PTX helpers ---------------------------------------------
__device__ __forceinline__ uint32_t smem_u32(const void* p) {
    uint32_t a;
    asm("{ .reg .u64 t; cvta.to.shared.u64 t, %1; cvt.u32.u64 %0, t; }" : "=r"(a) : "l"(p));
    return a;
}
__device__ __forceinline__ void cp16(uint32_t dst, const void* src) {
    asm volatile("cp.async.cg.shared.global [%0], [%1], 16;" :: "r"(dst), "l"(src));
}
#define CP_COMMIT() asm volatile("cp.async.commit_group;" ::: "memory")

__device__ __forceinline__ void ldsm4(uint32_t* r, uint32_t addr) {
    asm volatile("ldmatrix.sync.aligned.m8n8.x4.shared.b16 {%0,%1,%2,%3}, [%4];"
                 : "=r"(r[0]), "=r"(r[1]), "=r"(r[2]), "=r"(r[3]) : "r"(addr));
}
__device__ __forceinline__ void mma16816(float* c, const uint32_t* a, const uint32_t* b) {
    asm volatile(
        "mma.sync.aligned.m16n8k16.row.col.f32.f16.f16.f32 "
        "{%0,%1,%2,%3}, {%4,%5,%6,%7}, {%8,%9}, {%0,%1,%2,%3};\n"
        : "+f"(c[0]), "+f"(c[1]), "+f"(c[2]), "+f"(c[3])
        : "r"(a[0]), "r"(a[1]), "r"(a[2]), "r"(a[3]), "r"(b[0]), "r"(b[1]));
}

__device__ __forceinline__ void split1h(float v, __half& h, __half& l) {
    h = __float2half_rn(v);
    l = __float2half_rn(v - __half2float(h));
}

// ---------------- GEMM: C = sum3( A(hi/lo)[M,K] * B(hi/lo)[N,K]^T ) --------
// Block 128x128x32, 8 warps (2Mx4N), warp tile 64x32 via m16n8k16 HMMA.
// MODE 0: fp32*alpha  MODE 1: split fp16 (Chi/Clo [M,N])  MODE 2: split fp16 V^T
#define BM 128
#define BN 128
#define BK 32
static constexpr uint32_t TILE_B = BM * BK * 2;   // 8192 bytes per half-tile
static constexpr uint32_t STAGE  = 4 * TILE_B;    // Ah, Al, Bh, Bl = 32 KB
static constexpr uint32_t GSMEM  = 2 * STAGE;     // 64 KB double buffered

// rows are 64B (32 fp16); chunk c in 0..3; XOR swizzle for conflict-free LDSM
__device__ __forceinline__ uint32_t swz(int r, int c) {
    return (uint32_t)(r * 64 + ((c ^ ((r >> 1) & 3)) << 4));
}

__device__ __forceinline__ void load_stage_g(
    uint32_t s0, const __half* __restrict__ Ahi, const __half* __restrict__ Alo,
    const __half* __restrict__ Bhi, const __half* __restrict__ Blo,
    size_t rowA0, size_t rowB0, int K, int k0, int tid)
{
#pragma unroll
    for (int i = 0; i < 8; i++) {
        int q = tid + i * 256;
        int tile = q >> 9;            // 0:Ah 1:Al 2:Bh 3:Bl
        int idx = q & 511;
        int r = idx >> 2, c = idx & 3;
        const __half* g = (tile == 0) ? Ahi : (tile == 1) ? Alo
                         : (tile == 2) ? Bhi : Blo;
        size_t row0 = (tile < 2) ? rowA0 : rowB0;
        cp16(s0 + (uint32_t)tile * TILE_B + swz(r, c),
             g + (row0 + r) * (size_t)K + k0 + c * 8);
    }
    CP_COMMIT();
}

template <int MODE>
__global__ __launch_bounds__(256) void gemm_fp16x3(
    const __half* __restrict__ Ahi, const __half* __restrict__ Alo,
    const __half* __restrict__ Bhi, const __half* __restrict__ Blo,
    float* __restrict__ Cf, __half* __restrict__ Chi, __half* __restrict__ Clo,
    int N, int K, float alpha, size_t sA, size_t sB, size_t sC)
{
    extern __shared__ char smem[];
    const uint32_t sb = smem_u32(smem);
    const int tid = threadIdx.x, lane = tid & 31, wid = tid >> 5;
    const int wm = wid >> 2, wn = wid & 3;
    const int bz = blockIdx.z;
    Ahi += (size_t)bz * sA; Alo += (size_t)bz * sA;
    Bhi += (size_t)bz * sB; Blo += (size_t)bz * sB;
    const size_t rowA0 = (size_t)blockIdx.y * BM;
    const size_t rowB0 = (size_t)blockIdx.x * BN;

    float acc[4][4][4];
#pragma unroll
    for (int a = 0; a < 4; a++)
#pragma unroll
        for (int b = 0; b < 4; b++)
#pragma unroll
            for (int k = 0; k < 4; k++) acc[a][b][k] = 0.0f;

    const int T = K / BK;
    load_stage_g(sb, Ahi, Alo, Bhi, Blo, rowA0, rowB0, K, 0, tid);

    for (int t = 0; t < T; t++) {
        if (t + 1 < T) {
            load_stage_g(sb + (uint32_t)((t + 1) & 1) * STAGE,
                         Ahi, Alo, Bhi, Blo, rowA0, rowB0, K, (t + 1) * BK, tid);
            asm volatile("cp.async.wait_group 1;" ::: "memory");
        } else {
            asm volatile("cp.async.wait_group 0;" ::: "memory");
        }
        __syncthreads();

        const uint32_t s0 = sb + (uint32_t)(t & 1) * STAGE;
#pragma unroll
        for (int st = 0; st < 2; st++) {
            uint32_t ah[4][4], al[4][4], bh[4][2], bl[4][2];
            const int ra = lane & 15;
            const int ca = 2 * st + (lane >> 4);
#pragma unroll
            for (int mf = 0; mf < 4; mf++) {
                int r = wm * 64 + mf * 16 + ra;
                ldsm4(ah[mf], s0 + swz(r, ca));
                ldsm4(al[mf], s0 + TILE_B + swz(r, ca));
            }
            const int rb = (lane & 7) + ((lane >> 4) << 3);
            const int cb = 2 * st + ((lane >> 3) & 1);
#pragma unroll
            for (int p = 0; p < 2; p++) {
                uint32_t tmp[4];
                int r = wn * 32 + p * 16 + rb;
                ldsm4(tmp, s0 + 2 * TILE_B + swz(r, cb));
                bh[2 * p][0] = tmp[0]; bh[2 * p][1] = tmp[1];
                bh[2 * p + 1][0] = tmp[2]; bh[2 * p + 1][1] = tmp[3];
                ldsm4(tmp, s0 + 3 * TILE_B + swz(r, cb));
                bl[2 * p][0] = tmp[0]; bl[2 * p][1] = tmp[1];
                bl[2 * p + 1][0] = tmp[2]; bl[2 * p + 1][1] = tmp[3];
            }
#pragma unroll
            for (int mf = 0; mf < 4; mf++)
#pragma unroll
                for (int nf = 0; nf < 4; nf++) mma16816(acc[mf][nf], ah[mf], bh[nf]);
#pragma unroll
            for (int mf = 0; mf < 4; mf++)
#pragma unroll
                for (int nf = 0; nf < 4; nf++) mma16816(acc[mf][nf], al[mf], bh[nf]);
#pragma unroll
            for (int mf = 0; mf < 4; mf++)
#pragma unroll
                for (int nf = 0; nf < 4; nf++) mma16816(acc[mf][nf], ah[mf], bl[nf]);
        }
        __syncthreads();
    }

    // ---- epilogue ----
    const int qr = lane >> 2;
    const int qc = (lane & 3) * 2;
#pragma unroll
    for (int mf = 0; mf < 4; mf++) {
#pragma unroll
        for (int nf = 0; nf < 4; nf++) {
            size_t r0 = rowA0 + wm * 64 + mf * 16 + qr;
            int c0 = (int)rowB0 + wn * 32 + nf * 8 + qc;
            float v0 = acc[mf][nf][0] * alpha, v1 = acc[mf][nf][1] * alpha;
            float v2 = acc[mf][nf][2] * alpha, v3 = acc[mf][nf][3] * alpha;
            if (MODE == 0) {
                float* base = Cf + (size_t)bz * sC;
                *(float2*)(base + r0 * N + c0)       = make_float2(v0, v1);
                *(float2*)(base + (r0 + 8) * N + c0) = make_float2(v2, v3);
            } else if (MODE == 1) {
                __half h0, l0, h1, l1, h2, l2, h3, l3;
                split1h(v0, h0, l0); split1h(v1, h1, l1);
                split1h(v2, h2, l2); split1h(v3, h3, l3);
                size_t o1 = (size_t)bz * sC + r0 * N + c0;
                size_t o2 = (size_t)bz * sC + (r0 + 8) * N + c0;
                *(__half2*)(Chi + o1) = __halves2half2(h0, h1);
                *(__half2*)(Clo + o1) = __halves2half2(l0, l1);
                *(__half2*)(Chi + o2) = __halves2half2(h2, h3);
                *(__half2*)(Clo + o2) = __halves2half2(l2, l3);
            } else {  // MODE 2: write transposed V^T[b][d][s]
                int b = (int)(r0 >> 12);
                int sI = (int)(r0 & (SEQ - 1));
                size_t cbase = (size_t)b * ((size_t)ED * SEQ);
                __half h, l;
                split1h(v0, h, l);
                Chi[cbase + (size_t)c0 * SEQ + sI] = h;
                Clo[cbase + (size_t)c0 * SEQ + sI] = l;
                split1h(v1, h, l);
                Chi[cbase + (size_t)(c0 + 1) * SEQ + sI] = h;
                Clo[cbase + (size_t)(c0 + 1) * SEQ + sI] = l;
                split1h(v2, h, l);
                Chi[cbase + (size_t)c0 * SEQ + sI + 8] = h;
                Clo[cbase + (size_t)c0 * SEQ + sI + 8] = l;
                split1h(v3, h, l);
                Chi[cbase + (size_t)(c0 + 1) * SEQ + sI + 8] = h;
                Clo[cbase + (size_t)(c0 + 1) * SEQ + sI + 8] = l;
            }
        }
    }
}

// ---------------- split fp32 -> (hi, lo) fp16 ------------------------------
__global__ __launch_bounds__(256) void split_kernel(
    const float* __restrict__ X, __half* __restrict__ H,
    __half* __restrict__ L, int n4)
{
    int i = blockIdx.x * blockDim.x + threadIdx.x;
    if (i >= n4) return;
    float4 v = ((const float4*)X)[i];
    __half h0, l0, h1, l1, h2, l2, h3, l3;
    split1h(v.x, h0, l0); split1h(v.y, h1, l1);
    split1h(v.z, h2, l2); split1h(v.w, h3, l3);
    __half2 hu[2] = { __halves2half2(h0, h1), __halves2half2(h2, h3) };
    __half2 lu[2] = { __halves2half2(l0, l1), __halves2half2(l2, l3) };
    ((uint2*)H)[i] = *(uint2*)hu;
    ((uint2*)L)[i] = *(uint2*)lu;
}

// ---------------- softmax: fp32 S row -> split fp16 P ----------------------
__global__ __launch_bounds__(256) void softmax_row(
    const float* __restrict__ Sm, __half* __restrict__ Ph,
    __half* __restrict__ Pl)
{
    const size_t rb = (size_t)blockIdx.x * SEQ;
    const float* p = Sm + rb;
    const int tid = threadIdx.x;
    __shared__ float red[8];

    float4 v[4];
    float m = -1e30f;
#pragma unroll
    for (int i = 0; i < 4; i++) {
        v[i] = *(const float4*)(p + (size_t)(i * 256 + tid) * 4);
        m = fmaxf(m, fmaxf(fmaxf(v[i].x, v[i].y), fmaxf(v[i].z, v[i].w)));
    }
#pragma unroll
    for (int o = 16; o; o >>= 1) m = fmaxf(m, __shfl_xor_sync(0xFFFFFFFFu, m, o));
    if ((tid & 31) == 0) red[tid >> 5] = m;
    __syncthreads();
    m = red[0];
#pragma unroll
    for (int w = 1; w < 8; w++) m = fmaxf(m, red[w]);
    __syncthreads();

    float s = 0.0f;
#pragma unroll
    for (int i = 0; i < 4; i++) {
        v[i].x = __expf(v[i].x - m); v[i].y = __expf(v[i].y - m);
        v[i].z = __expf(v[i].z - m); v[i].w = __expf(v[i].w - m);
        s += v[i].x + v[i].y + v[i].z + v[i].w;
    }
#pragma unroll
    for (int o = 16; o; o >>= 1) s += __shfl_xor_sync(0xFFFFFFFFu, s, o);
    if ((tid & 31) == 0) red[tid >> 5] = s;
    __syncthreads();
    s = red[0];
#pragma unroll
    for (int w = 1; w < 8; w++) s += red[w];
    const float r = 1.0f / s;

#pragma unroll
    for (int i = 0; i < 4; i++) {
        float a0 = v[i].x * r, a1 = v[i].y * r, a2 = v[i].z * r, a3 = v[i].w * r;
        __half h0, l0, h1, l1, h2, l2, h3, l3;
        split1h(a0, h0, l0); split1h(a1, h1, l1);
        split1h(a2, h2, l2); split1h(a3, h3, l3);
        size_t idx = rb + (size_t)(i * 256 + tid) * 4;
        __half2 hu[2] = { __halves2half2(h0, h1), __halves2half2(h2, h3) };
        __half2 lu[2] = { __halves2half2(l0, l1), __halves2half2(l2, l3) };
        *(uint2*)(Ph + idx) = *(uint2*)hu;
        *(uint2*)(Pl + idx) = *(uint2*)lu;
    }
}

// ---------------------------------------------------------------------------
extern "C" void kernel_launch(void* const* d_in, const int* in_sizes, int n_in,
                              void* d_out, int out_size)
{
    const float* x  = (const float*)d_in[0];
    const float* W[4] = { (const float*)d_in[1], (const float*)d_in[2],
                          (const float*)d_in[3], (const float*)d_in[4] };
    float* out = (float*)d_out;

    __half *xhi, *xlo, *Whi, *Wlo, *Qhi, *Qlo, *Khi, *Klo;
    __half *Vthi, *Vtlo, *Ohi, *Olo, *Phi, *Plo;
    float* S;
    cudaGetSymbolAddress((void**)&xhi, g_xhi);  cudaGetSymbolAddress((void**)&xlo, g_xlo);
    cudaGetSymbolAddress((void**)&Whi, g_Whi);  cudaGetSymbolAddress((void**)&Wlo, g_Wlo);
    cudaGetSymbolAddress((void**)&Qhi, g_Qhi);  cudaGetSymbolAddress((void**)&Qlo, g_Qlo);
    cudaGetSymbolAddress((void**)&Khi, g_Khi);  cudaGetSymbolAddress((void**)&Klo, g_Klo);
    cudaGetSymbolAddress((void**)&Vthi, g_Vthi); cudaGetSymbolAddress((void**)&Vtlo, g_Vtlo);
    cudaGetSymbolAddress((void**)&Ohi, g_Ohi);  cudaGetSymbolAddress((void**)&Olo, g_Olo);
    cudaGetSymbolAddress((void**)&Phi, g_Phi);  cudaGetSymbolAddress((void**)&Plo, g_Plo);
    cudaGetSymbolAddress((void**)&S,   g_S);

    cudaFuncSetAttribute(gemm_fp16x3<0>, cudaFuncAttributeMaxDynamicSharedMemorySize, GSMEM);
    cudaFuncSetAttribute(gemm_fp16x3<1>, cudaFuncAttributeMaxDynamicSharedMemorySize, GSMEM);
    cudaFuncSetAttribute(gemm_fp16x3<2>, cudaFuncAttributeMaxDynamicSharedMemorySize, GSMEM);

    const size_t WSZ = (size_t)ED * ED;
    const size_t sQKV = (size_t)SEQ * ED;
    const size_t sS   = (size_t)SEQ * SEQ;

    // 1) split inputs to (hi, lo) fp16
    {
        int n4 = (MTOT * ED) / 4;
        split_kernel<<<(n4 + 255) / 256, 256>>>(x, xhi, xlo, n4);
        int w4 = (int)(WSZ / 4);
        for (int i = 0; i < 4; i++)
            split_kernel<<<(w4 + 255) / 256, 256>>>(W[i], Whi + i * WSZ, Wlo + i * WSZ, w4);
    }

    // 2) projections (M=8192, N=1024, K=1024)
    {
        dim3 grid(ED / BN, MTOT / BM, 1);
        gemm_fp16x3<1><<<grid, 256, GSMEM>>>(xhi, xlo, Whi + 0 * WSZ, Wlo + 0 * WSZ,
            nullptr, Qhi, Qlo, ED, ED, 1.0f, 0, 0, 0);
        gemm_fp16x3<1><<<grid, 256, GSMEM>>>(xhi, xlo, Whi + 1 * WSZ, Wlo + 1 * WSZ,
            nullptr, Khi, Klo, ED, ED, 1.0f, 0, 0, 0);
        gemm_fp16x3<2><<<grid, 256, GSMEM>>>(xhi, xlo, Whi + 2 * WSZ, Wlo + 2 * WSZ,
            nullptr, Vthi, Vtlo, ED, ED, 1.0f, 0, 0, 0);
    }

    // 3) scores S = Q K^T / 32 (batched, M=N=4096, K=1024)
    {
        dim3 grid(SEQ / BN, SEQ / BM, NB);
        gemm_fp16x3<0><<<grid, 256, GSMEM>>>(Qhi, Qlo, Khi, Klo,
            S, nullptr, nullptr, SEQ, ED, 0.03125f, sQKV, sQKV, sS);
    }

    // 4) softmax -> split fp16 P
    softmax_row<<<NB * SEQ, 256>>>(S, Phi, Plo);

    // 5) O = P V (batched, M=4096, N=1024, K=4096; B = V^T is K-major)
    {
        dim3 grid(ED / BN, SEQ / BM, NB);
        gemm_fp16x3<1><<<grid, 256, GSMEM>>>(Phi, Plo, Vthi, Vtlo,
            nullptr, Ohi, Olo, ED, SEQ, 1.0f, sS, sQKV, sQKV);
    }

    // 6) out = O Wo^T (M=8192, N=1024, K=1024), fp32 result
    {
        dim3 grid(ED / BN, MTOT / BM, 1);
        gemm_fp16x3<0><<<grid, 256, GSMEM>>>(Ohi, Olo, Whi + 3 * WSZ, Wlo + 3 * WSZ,
            out, nullptr, nullptr, ED, ED, 1.0f, 0, 0, 0);
    }
}